// round 1
// baseline (speedup 1.0000x reference)
#include <cuda_runtime.h>
#include <math.h>

// Problem dims
constexpr int BATCH = 2;
constexpr int SEQ   = 1024;
constexpr int DM    = 1024;   // D_MODEL
constexpr int DIN   = 2048;   // D_INNER
constexpr int NST   = 16;     // D_STATE
constexpr int FH    = 2752;   // FFN_HIDDEN
constexpr int ROWS  = BATCH * SEQ;  // 2048

// Scratch (device globals: allocation-free)
__device__ float g_h [ROWS * DM];    // rmsnorm output (h, then hn)
__device__ float g_a [ROWS * DIN];   // z (gated in place)
__device__ float g_b [ROWS * DIN];   // gate preact, then dt
__device__ float g_y [ROWS * DIN];   // scan output
__device__ float g_x2[ROWS * DM];    // residual after out_proj
__device__ float g_bc[ROWS * 2 * NST];
__device__ float g_g [ROWS * FH];    // ffn gate (then silu*up)
__device__ float g_u [ROWS * FH];    // ffn up

// ---------------------------------------------------------------------------
// RMSNorm: one block per row, 256 threads, 4 floats/thread (D = 1024)
// ---------------------------------------------------------------------------
__global__ void __launch_bounds__(256) rmsnorm_kernel(
    const float* __restrict__ x, const float* __restrict__ w, float* __restrict__ out)
{
    __shared__ float red[8];
    const int row = blockIdx.x;
    const int tid = threadIdx.x;
    const float4 v = ((const float4*)(x + (size_t)row * DM))[tid];
    float s = v.x*v.x + v.y*v.y + v.z*v.z + v.w*v.w;
    #pragma unroll
    for (int o = 16; o; o >>= 1) s += __shfl_xor_sync(0xffffffffu, s, o);
    if ((tid & 31) == 0) red[tid >> 5] = s;
    __syncthreads();
    if (tid < 8) {
        float t = red[tid];
        #pragma unroll
        for (int o = 4; o; o >>= 1) t += __shfl_xor_sync(0xffu, t, o);
        if (tid == 0) red[0] = t;
    }
    __syncthreads();
    const float scale = rsqrtf(red[0] * (1.0f / DM) + 1e-6f);
    const float4 wv = ((const float4*)w)[tid];
    float4 o4;
    o4.x = v.x * scale * wv.x;
    o4.y = v.y * scale * wv.y;
    o4.z = v.z * scale * wv.z;
    o4.w = v.w * scale * wv.w;
    ((float4*)(out + (size_t)row * DM))[tid] = o4;
}

// ---------------------------------------------------------------------------
// SGEMM: C[M,N] = A[M,K] @ W[N,K]^T (+ ADDSRC).  128x128 tile, BK=8,
// 256 threads, 8x8 outputs/thread.  M assumed multiple of 128, K multiple
// of 8; N guarded (FH=2752 = 21.5 * 128).
// ---------------------------------------------------------------------------
template<bool ADD>
__global__ void __launch_bounds__(256) sgemm_kernel(
    const float* __restrict__ A, const float* __restrict__ W,
    const float* __restrict__ ADDSRC, float* __restrict__ C,
    int M, int N, int K)
{
    __shared__ float As[8][128];
    __shared__ float Bs[8][128];
    const int tid = threadIdx.x;
    const int bm = blockIdx.y * 128;
    const int bn = blockIdx.x * 128;
    const int lr = tid >> 1;          // 0..127 row in tile
    const int lk = (tid & 1) << 2;    // 0 or 4
    const int tx = tid & 15;
    const int ty = tid >> 4;

    float acc[8][8];
    #pragma unroll
    for (int i = 0; i < 8; i++)
        #pragma unroll
        for (int j = 0; j < 8; j++) acc[i][j] = 0.0f;

    const float* Ap = A + (size_t)(bm + lr) * K + lk;
    const bool wvalid = (bn + lr) < N;
    const float* Wp = W + (size_t)(wvalid ? (bn + lr) : 0) * K + lk;

    for (int k0 = 0; k0 < K; k0 += 8) {
        const float4 av = *(const float4*)(Ap + k0);
        const float4 bv = wvalid ? *(const float4*)(Wp + k0)
                                 : make_float4(0.f, 0.f, 0.f, 0.f);
        __syncthreads();
        As[lk + 0][lr] = av.x; As[lk + 1][lr] = av.y;
        As[lk + 2][lr] = av.z; As[lk + 3][lr] = av.w;
        Bs[lk + 0][lr] = bv.x; Bs[lk + 1][lr] = bv.y;
        Bs[lk + 2][lr] = bv.z; Bs[lk + 3][lr] = bv.w;
        __syncthreads();
        #pragma unroll
        for (int kk = 0; kk < 8; kk++) {
            float a[8], b[8];
            *(float4*)&a[0] = *(const float4*)&As[kk][ty * 8];
            *(float4*)&a[4] = *(const float4*)&As[kk][ty * 8 + 4];
            *(float4*)&b[0] = *(const float4*)&Bs[kk][tx * 8];
            *(float4*)&b[4] = *(const float4*)&Bs[kk][tx * 8 + 4];
            #pragma unroll
            for (int i = 0; i < 8; i++)
                #pragma unroll
                for (int j = 0; j < 8; j++)
                    acc[i][j] = fmaf(a[i], b[j], acc[i][j]);
        }
    }

    #pragma unroll
    for (int i = 0; i < 8; i++) {
        const int row = bm + ty * 8 + i;
        #pragma unroll
        for (int j = 0; j < 8; j += 4) {
            const int col = bn + tx * 8 + j;
            if (col + 3 < N) {
                float4 v = make_float4(acc[i][j], acc[i][j+1], acc[i][j+2], acc[i][j+3]);
                if (ADD) {
                    const float4 r = *(const float4*)&ADDSRC[(size_t)row * N + col];
                    v.x += r.x; v.y += r.y; v.z += r.z; v.w += r.w;
                }
                *(float4*)&C[(size_t)row * N + col] = v;
            } else {
                #pragma unroll
                for (int jj = 0; jj < 4; jj++) {
                    if (col + jj < N) {
                        float v = acc[i][j + jj];
                        if (ADD) v += ADDSRC[(size_t)row * N + col + jj];
                        C[(size_t)row * N + col + jj] = v;
                    }
                }
            }
        }
    }
}

// ---------------------------------------------------------------------------
// Elementwise kernels
// ---------------------------------------------------------------------------
__global__ void gate_mul_kernel()  // g_a = g_a * sigmoid(g_b), n = ROWS*DIN
{
    const int i = blockIdx.x * 256 + threadIdx.x;
    const float g = g_b[i];
    g_a[i] *= 1.0f / (1.0f + expf(-g));
}

__global__ void softplus_kernel(const float* __restrict__ dt_b)  // g_b = softplus(g_b + dt_b[col])
{
    const int i = blockIdx.x * 256 + threadIdx.x;
    const float v = g_b[i] + dt_b[i & (DIN - 1)];
    g_b[i] = (v > 20.0f) ? v : log1pf(expf(v));
}

__global__ void silu_mul_kernel()  // g_g = silu(g_g) * g_u, n = ROWS*FH
{
    const int i = blockIdx.x * 256 + threadIdx.x;
    const float g = g_g[i];
    const float u = g_u[i];
    g_g[i] = g * (1.0f / (1.0f + expf(-g))) * u;
}

// ---------------------------------------------------------------------------
// BC = z @ x_proj_w^T   (M=ROWS, N=32, K=DIN).  One block per row, 8 warps,
// each warp computes 4 of the 32 outputs via lane-strided K + shfl reduce.
// ---------------------------------------------------------------------------
__global__ void __launch_bounds__(256) bc_kernel(const float* __restrict__ Wx)
{
    const int row  = blockIdx.x;
    const int tid  = threadIdx.x;
    const int w    = tid >> 5;
    const int lane = tid & 31;
    const float* zr = g_a + (size_t)row * DIN;
    float acc[4] = {0.f, 0.f, 0.f, 0.f};
    for (int k = lane; k < DIN; k += 32) {
        const float zv = zr[k];
        #pragma unroll
        for (int j = 0; j < 4; j++)
            acc[j] = fmaf(zv, Wx[(size_t)(w * 4 + j) * DIN + k], acc[j]);
    }
    #pragma unroll
    for (int j = 0; j < 4; j++) {
        float s = acc[j];
        #pragma unroll
        for (int o = 16; o; o >>= 1) s += __shfl_xor_sync(0xffffffffu, s, o);
        if (lane == 0) g_bc[(size_t)row * 32 + w * 4 + j] = s;
    }
}

// ---------------------------------------------------------------------------
// Selective scan.  16 lanes per channel (one state index n per lane),
// sequential over t.  16 channels per 256-thread block, grid = 256.
//   state = exp(dt * A_n) * state + dt * z * B_n
//   y[t]  = sum_n state * C_n + z * Dp
// ---------------------------------------------------------------------------
__global__ void __launch_bounds__(256) scan_kernel(
    const float* __restrict__ A_log, const float* __restrict__ Dp)
{
    const int tid = threadIdx.x;
    const int ch  = blockIdx.x * 16 + (tid >> 4);   // 0 .. 4095
    const int n   = tid & 15;
    const int b   = ch / DIN;
    const int e   = ch % DIN;

    const float An  = -__expf(A_log[(size_t)e * NST + n]);
    const float dpe = Dp[e];

    const float* dtp = g_b  + (size_t)b * SEQ * DIN + e;
    const float* zp  = g_a  + (size_t)b * SEQ * DIN + e;
    const float* bcp = g_bc + (size_t)b * SEQ * 32;
    float*       yp  = g_y  + (size_t)b * SEQ * DIN + e;

    float state = 0.0f;
    for (int t = 0; t < SEQ; t++) {
        const float dtv = dtp[(size_t)t * DIN];
        const float zv  = zp [(size_t)t * DIN];
        const float Bn  = bcp[t * 32 + n];
        const float Cn  = bcp[t * 32 + 16 + n];
        state = __expf(dtv * An) * state + dtv * zv * Bn;
        float s = state * Cn;
        s += __shfl_xor_sync(0xffffffffu, s, 8);
        s += __shfl_xor_sync(0xffffffffu, s, 4);
        s += __shfl_xor_sync(0xffffffffu, s, 2);
        s += __shfl_xor_sync(0xffffffffu, s, 1);
        if (n == 0) yp[(size_t)t * DIN] = s + zv * dpe;
    }
}

// ---------------------------------------------------------------------------
// Launch
// ---------------------------------------------------------------------------
extern "C" void kernel_launch(void* const* d_in, const int* in_sizes, int n_in,
                              void* d_out, int out_size)
{
    const float* x          = (const float*)d_in[0];
    const float* norm1_w    = (const float*)d_in[1];
    const float* in_proj_w  = (const float*)d_in[2];
    const float* gate_proj_w= (const float*)d_in[3];
    const float* dt_w       = (const float*)d_in[4];
    const float* dt_b       = (const float*)d_in[5];
    const float* x_proj_w   = (const float*)d_in[6];
    const float* A_log      = (const float*)d_in[7];
    const float* Dp         = (const float*)d_in[8];
    const float* out_proj_w = (const float*)d_in[9];
    const float* ffn_norm_w = (const float*)d_in[10];
    const float* ffn_gate_w = (const float*)d_in[11];
    const float* ffn_up_w   = (const float*)d_in[12];
    const float* ffn_down_w = (const float*)d_in[13];
    float* out = (float*)d_out;

    float *h, *a, *bb, *y, *x2, *gg, *uu;
    cudaGetSymbolAddress((void**)&h,  g_h);
    cudaGetSymbolAddress((void**)&a,  g_a);
    cudaGetSymbolAddress((void**)&bb, g_b);
    cudaGetSymbolAddress((void**)&y,  g_y);
    cudaGetSymbolAddress((void**)&x2, g_x2);
    cudaGetSymbolAddress((void**)&gg, g_g);
    cudaGetSymbolAddress((void**)&uu, g_u);

    const dim3 blk(256);

    // 1. h = rmsnorm(x)
    rmsnorm_kernel<<<ROWS, blk>>>(x, norm1_w, h);

    // 2. z = h @ in_proj^T ; gate = h @ gate_proj^T ; z *= sigmoid(gate)
    sgemm_kernel<false><<<dim3(DIN / 128, ROWS / 128), blk>>>(h, in_proj_w,  nullptr, a,  ROWS, DIN, DM);
    sgemm_kernel<false><<<dim3(DIN / 128, ROWS / 128), blk>>>(h, gate_proj_w, nullptr, bb, ROWS, DIN, DM);
    gate_mul_kernel<<<(ROWS * DIN) / 256, blk>>>();

    // 3. dt = softplus(z @ dt_w^T + dt_b)
    sgemm_kernel<false><<<dim3(DIN / 128, ROWS / 128), blk>>>(a, dt_w, nullptr, bb, ROWS, DIN, DIN);
    softplus_kernel<<<(ROWS * DIN) / 256, blk>>>(dt_b);

    // 4. BC = z @ x_proj^T
    bc_kernel<<<ROWS, blk>>>(x_proj_w);

    // 5. selective scan -> y
    scan_kernel<<<(BATCH * DIN) / 16, blk>>>(A_log, Dp);

    // 6. x2 = x + y @ out_proj^T
    sgemm_kernel<true><<<dim3(DM / 128, ROWS / 128), blk>>>(y, out_proj_w, x, x2, ROWS, DM, DIN);

    // 7. hn = rmsnorm(x2)
    rmsnorm_kernel<<<ROWS, blk>>>(x2, ffn_norm_w, h);

    // 8. FFN: gg = silu(hn @ Wg^T) * (hn @ Wu^T)
    sgemm_kernel<false><<<dim3((FH + 127) / 128, ROWS / 128), blk>>>(h, ffn_gate_w, nullptr, gg, ROWS, FH, DM);
    sgemm_kernel<false><<<dim3((FH + 127) / 128, ROWS / 128), blk>>>(h, ffn_up_w,   nullptr, uu, ROWS, FH, DM);
    silu_mul_kernel<<<(ROWS * FH) / 256, blk>>>();

    // 9. out = x2 + gg @ Wd^T
    sgemm_kernel<true><<<dim3(DM / 128, ROWS / 128), blk>>>(gg, ffn_down_w, x2, out, ROWS, DM, FH);
}

// round 3
// speedup vs baseline: 2.2601x; 2.2601x over previous
#include <cuda_runtime.h>
#include <math.h>
#include <stdint.h>

// Problem dims
constexpr int BATCH = 2;
constexpr int SEQ   = 1024;
constexpr int DM    = 1024;
constexpr int DIN   = 2048;
constexpr int NST   = 16;
constexpr int FH    = 2752;
constexpr int ROWS  = BATCH * SEQ;  // 2048

// Scratch
__device__ float g_h [ROWS * DM];
__device__ float g_a [ROWS * DIN];
__device__ float g_b [ROWS * DIN];
__device__ float g_y [ROWS * DIN];
__device__ float g_x2[ROWS * DM];
__device__ float g_bc[ROWS * 2 * NST];
__device__ float g_g [ROWS * FH];

// ---------------------------------------------------------------------------
// tf32 helpers (sm_80+ baseline features only — no tcgen05, no 'a' features)
// ---------------------------------------------------------------------------
__device__ __forceinline__ uint32_t f2tf32(float f) {
    uint32_t u;
    asm("cvt.rna.tf32.f32 %0, %1;" : "=r"(u) : "f"(f));
    return u;
}

__device__ __forceinline__ void mma_tf32(float c[4],
                                         uint32_t a0, uint32_t a1, uint32_t a2, uint32_t a3,
                                         uint32_t b0, uint32_t b1) {
    asm volatile(
        "mma.sync.aligned.m16n8k8.row.col.f32.tf32.tf32.f32 "
        "{%0,%1,%2,%3}, {%4,%5,%6,%7}, {%8,%9}, {%0,%1,%2,%3};"
        : "+f"(c[0]), "+f"(c[1]), "+f"(c[2]), "+f"(c[3])
        : "r"(a0), "r"(a1), "r"(a2), "r"(a3), "r"(b0), "r"(b1));
}

enum { EP_NONE = 0, EP_ADD, EP_GATEMUL, EP_SOFTPLUS, EP_SILUMUL };

__device__ __forceinline__ float sigm(float x) { return 1.0f / (1.0f + expf(-x)); }
__device__ __forceinline__ float sftp(float x) { return (x > 20.0f) ? x : log1pf(expf(x)); }

// ---------------------------------------------------------------------------
// tf32 GEMM: C[M,N] = epilogue(A[M,K] @ W[N,K]^T)
// Block 128x128, BK=16, 4 warps, warp tile 64x64 (4 m-tiles x 8 n-tiles of
// m16n8k8).  smem stride 20 floats -> conflict-free fragment loads.
// Double-buffered, one __syncthreads per stage.
// ---------------------------------------------------------------------------
constexpr int BK = 16;
constexpr int LDS_STRIDE = 20;   // 16 + 4 pad: (r*20 + k) % 32 distinct for r<8,k<4

template<int EP>
__global__ void __launch_bounds__(128) mma_gemm(
    const float* __restrict__ A, const float* __restrict__ W,
    const float* __restrict__ R, const float* __restrict__ bias,
    float* __restrict__ C, int M, int N, int K)
{
    __shared__ float As[2][128 * LDS_STRIDE];
    __shared__ float Bs[2][128 * LDS_STRIDE];

    const int tid  = threadIdx.x;
    const int wid  = tid >> 5, lane = tid & 31;
    const int wm   = wid >> 1, wn = wid & 1;
    const int bm   = blockIdx.y << 7, bn = blockIdx.x << 7;
    const int lr   = lane >> 2, lc = lane & 3;

    float acc[4][8][4];
    #pragma unroll
    for (int i = 0; i < 4; i++)
        #pragma unroll
        for (int j = 0; j < 8; j++)
            #pragma unroll
            for (int q = 0; q < 4; q++) acc[i][j][q] = 0.0f;

    // Global-load mapping: idx = tid + 128*j -> row = idx>>2, kcol = (idx&3)*4
    const int row0 = tid >> 2;          // +32 per j
    const int kcol = (tid & 3) << 2;

    const int NS = K >> 4;              // K % 16 == 0 for all our shapes

    float4 areg[4], breg[4];

    // Prefetch stage 0
    #pragma unroll
    for (int j = 0; j < 4; j++) {
        const int row = row0 + 32 * j;
        areg[j] = *(const float4*)(A + (size_t)(bm + row) * K + kcol);
        breg[j] = (bn + row < N)
                ? *(const float4*)(W + (size_t)(bn + row) * K + kcol)
                : make_float4(0.f, 0.f, 0.f, 0.f);
    }
    #pragma unroll
    for (int j = 0; j < 4; j++) {
        const int row = row0 + 32 * j;
        uint32_t* ap = (uint32_t*)&As[0][row * LDS_STRIDE + kcol];
        uint32_t* bp = (uint32_t*)&Bs[0][row * LDS_STRIDE + kcol];
        ap[0] = f2tf32(areg[j].x); ap[1] = f2tf32(areg[j].y);
        ap[2] = f2tf32(areg[j].z); ap[3] = f2tf32(areg[j].w);
        bp[0] = f2tf32(breg[j].x); bp[1] = f2tf32(breg[j].y);
        bp[2] = f2tf32(breg[j].z); bp[3] = f2tf32(breg[j].w);
    }
    __syncthreads();

    for (int ks = 0; ks < NS; ks++) {
        const int buf = ks & 1;

        // Prefetch next stage into registers (latency hidden under MMAs)
        if (ks + 1 < NS) {
            const int k0 = (ks + 1) << 4;
            #pragma unroll
            for (int j = 0; j < 4; j++) {
                const int row = row0 + 32 * j;
                areg[j] = *(const float4*)(A + (size_t)(bm + row) * K + k0 + kcol);
                breg[j] = (bn + row < N)
                        ? *(const float4*)(W + (size_t)(bn + row) * K + k0 + kcol)
                        : make_float4(0.f, 0.f, 0.f, 0.f);
            }
        }

        // Compute on current buffer: 2 ksteps of 8
        const uint32_t* Asb = (const uint32_t*)As[buf];
        const uint32_t* Bsb = (const uint32_t*)Bs[buf];
        #pragma unroll
        for (int kc = 0; kc < 2; kc++) {
            uint32_t af[4][4], bf[8][2];
            #pragma unroll
            for (int tm = 0; tm < 4; tm++) {
                const int base = (wm * 64 + tm * 16 + lr) * LDS_STRIDE + kc * 8 + lc;
                af[tm][0] = Asb[base];
                af[tm][1] = Asb[base + 8 * LDS_STRIDE];
                af[tm][2] = Asb[base + 4];
                af[tm][3] = Asb[base + 8 * LDS_STRIDE + 4];
            }
            #pragma unroll
            for (int tn = 0; tn < 8; tn++) {
                const int base = (wn * 64 + tn * 8 + lr) * LDS_STRIDE + kc * 8 + lc;
                bf[tn][0] = Bsb[base];
                bf[tn][1] = Bsb[base + 4];
            }
            #pragma unroll
            for (int tm = 0; tm < 4; tm++)
                #pragma unroll
                for (int tn = 0; tn < 8; tn++)
                    mma_tf32(acc[tm][tn], af[tm][0], af[tm][1], af[tm][2], af[tm][3],
                             bf[tn][0], bf[tn][1]);
        }

        // Store next stage
        if (ks + 1 < NS) {
            const int nb = buf ^ 1;
            #pragma unroll
            for (int j = 0; j < 4; j++) {
                const int row = row0 + 32 * j;
                uint32_t* ap = (uint32_t*)&As[nb][row * LDS_STRIDE + kcol];
                uint32_t* bp = (uint32_t*)&Bs[nb][row * LDS_STRIDE + kcol];
                ap[0] = f2tf32(areg[j].x); ap[1] = f2tf32(areg[j].y);
                ap[2] = f2tf32(areg[j].z); ap[3] = f2tf32(areg[j].w);
                bp[0] = f2tf32(breg[j].x); bp[1] = f2tf32(breg[j].y);
                bp[2] = f2tf32(breg[j].z); bp[3] = f2tf32(breg[j].w);
            }
            __syncthreads();
        }
    }

    // Epilogue
    #pragma unroll
    for (int tm = 0; tm < 4; tm++) {
        const int row = bm + wm * 64 + tm * 16 + lr;
        #pragma unroll
        for (int tn = 0; tn < 8; tn++) {
            const int col = bn + wn * 64 + tn * 8 + lc * 2;
            if (col < N) {
                const size_t o0 = (size_t)row * N + col;
                const size_t o1 = (size_t)(row + 8) * N + col;
                float2 v0 = make_float2(acc[tm][tn][0], acc[tm][tn][1]);
                float2 v1 = make_float2(acc[tm][tn][2], acc[tm][tn][3]);
                if (EP == EP_ADD) {
                    const float2 r0 = *(const float2*)(R + o0);
                    const float2 r1 = *(const float2*)(R + o1);
                    v0.x += r0.x; v0.y += r0.y; v1.x += r1.x; v1.y += r1.y;
                } else if (EP == EP_GATEMUL) {
                    const float2 r0 = *(const float2*)(R + o0);
                    const float2 r1 = *(const float2*)(R + o1);
                    v0.x = r0.x * sigm(v0.x); v0.y = r0.y * sigm(v0.y);
                    v1.x = r1.x * sigm(v1.x); v1.y = r1.y * sigm(v1.y);
                } else if (EP == EP_SOFTPLUS) {
                    const float2 bv = *(const float2*)(bias + col);
                    v0.x = sftp(v0.x + bv.x); v0.y = sftp(v0.y + bv.y);
                    v1.x = sftp(v1.x + bv.x); v1.y = sftp(v1.y + bv.y);
                } else if (EP == EP_SILUMUL) {
                    const float2 r0 = *(const float2*)(R + o0);
                    const float2 r1 = *(const float2*)(R + o1);
                    v0.x = r0.x * sigm(r0.x) * v0.x; v0.y = r0.y * sigm(r0.y) * v0.y;
                    v1.x = r1.x * sigm(r1.x) * v1.x; v1.y = r1.y * sigm(r1.y) * v1.y;
                }
                *(float2*)(C + o0) = v0;
                *(float2*)(C + o1) = v1;
            }
        }
    }
}

// ---------------------------------------------------------------------------
// RMSNorm
// ---------------------------------------------------------------------------
__global__ void __launch_bounds__(256) rmsnorm_kernel(
    const float* __restrict__ x, const float* __restrict__ w, float* __restrict__ out)
{
    __shared__ float red[8];
    const int row = blockIdx.x;
    const int tid = threadIdx.x;
    const float4 v = ((const float4*)(x + (size_t)row * DM))[tid];
    float s = v.x*v.x + v.y*v.y + v.z*v.z + v.w*v.w;
    #pragma unroll
    for (int o = 16; o; o >>= 1) s += __shfl_xor_sync(0xffffffffu, s, o);
    if ((tid & 31) == 0) red[tid >> 5] = s;
    __syncthreads();
    if (tid < 8) {
        float t = red[tid];
        #pragma unroll
        for (int o = 4; o; o >>= 1) t += __shfl_xor_sync(0xffu, t, o);
        if (tid == 0) red[0] = t;
    }
    __syncthreads();
    const float scale = rsqrtf(red[0] * (1.0f / DM) + 1e-6f);
    const float4 wv = ((const float4*)w)[tid];
    float4 o4;
    o4.x = v.x * scale * wv.x; o4.y = v.y * scale * wv.y;
    o4.z = v.z * scale * wv.z; o4.w = v.w * scale * wv.w;
    ((float4*)(out + (size_t)row * DM))[tid] = o4;
}

// ---------------------------------------------------------------------------
// BC = z @ x_proj^T (N=32, K=DIN)
// ---------------------------------------------------------------------------
__global__ void __launch_bounds__(256) bc_kernel(const float* __restrict__ Wx)
{
    const int row  = blockIdx.x;
    const int tid  = threadIdx.x;
    const int w    = tid >> 5;
    const int lane = tid & 31;
    const float* zr = g_a + (size_t)row * DIN;
    float acc[4] = {0.f, 0.f, 0.f, 0.f};
    for (int k = lane; k < DIN; k += 32) {
        const float zv = zr[k];
        #pragma unroll
        for (int j = 0; j < 4; j++)
            acc[j] = fmaf(zv, Wx[(size_t)(w * 4 + j) * DIN + k], acc[j]);
    }
    #pragma unroll
    for (int j = 0; j < 4; j++) {
        float s = acc[j];
        #pragma unroll
        for (int o = 16; o; o >>= 1) s += __shfl_xor_sync(0xffffffffu, s, o);
        if (lane == 0) g_bc[(size_t)row * 32 + w * 4 + j] = s;
    }
}

// ---------------------------------------------------------------------------
// Selective scan (16 lanes per channel)
// ---------------------------------------------------------------------------
__global__ void __launch_bounds__(256) scan_kernel(
    const float* __restrict__ A_log, const float* __restrict__ Dp)
{
    const int tid = threadIdx.x;
    const int ch  = blockIdx.x * 16 + (tid >> 4);
    const int n   = tid & 15;
    const int b   = ch / DIN;
    const int e   = ch % DIN;

    const float An  = -__expf(A_log[(size_t)e * NST + n]);
    const float dpe = Dp[e];

    const float* dtp = g_b  + (size_t)b * SEQ * DIN + e;
    const float* zp  = g_a  + (size_t)b * SEQ * DIN + e;
    const float* bcp = g_bc + (size_t)b * SEQ * 32;
    float*       yp  = g_y  + (size_t)b * SEQ * DIN + e;

    float state = 0.0f;
    for (int t = 0; t < SEQ; t++) {
        const float dtv = dtp[(size_t)t * DIN];
        const float zv  = zp [(size_t)t * DIN];
        const float Bn  = bcp[t * 32 + n];
        const float Cn  = bcp[t * 32 + 16 + n];
        state = __expf(dtv * An) * state + dtv * zv * Bn;
        float s = state * Cn;
        s += __shfl_xor_sync(0xffffffffu, s, 8);
        s += __shfl_xor_sync(0xffffffffu, s, 4);
        s += __shfl_xor_sync(0xffffffffu, s, 2);
        s += __shfl_xor_sync(0xffffffffu, s, 1);
        if (n == 0) yp[(size_t)t * DIN] = s + zv * dpe;
    }
}

// ---------------------------------------------------------------------------
// Launch
// ---------------------------------------------------------------------------
extern "C" void kernel_launch(void* const* d_in, const int* in_sizes, int n_in,
                              void* d_out, int out_size)
{
    const float* x          = (const float*)d_in[0];
    const float* norm1_w    = (const float*)d_in[1];
    const float* in_proj_w  = (const float*)d_in[2];
    const float* gate_proj_w= (const float*)d_in[3];
    const float* dt_w       = (const float*)d_in[4];
    const float* dt_b       = (const float*)d_in[5];
    const float* x_proj_w   = (const float*)d_in[6];
    const float* A_log      = (const float*)d_in[7];
    const float* Dp         = (const float*)d_in[8];
    const float* out_proj_w = (const float*)d_in[9];
    const float* ffn_norm_w = (const float*)d_in[10];
    const float* ffn_gate_w = (const float*)d_in[11];
    const float* ffn_up_w   = (const float*)d_in[12];
    const float* ffn_down_w = (const float*)d_in[13];
    float* out = (float*)d_out;

    float *h, *a, *bb, *y, *x2, *gg;
    cudaGetSymbolAddress((void**)&h,  g_h);
    cudaGetSymbolAddress((void**)&a,  g_a);
    cudaGetSymbolAddress((void**)&bb, g_b);
    cudaGetSymbolAddress((void**)&y,  g_y);
    cudaGetSymbolAddress((void**)&x2, g_x2);
    cudaGetSymbolAddress((void**)&gg, g_g);

    const dim3 blk128(128);
    const dim3 blk256(256);

    // 1. h = rmsnorm(x)
    rmsnorm_kernel<<<ROWS, blk256>>>(x, norm1_w, h);

    // 2. z = h @ in_proj^T ; z *= sigmoid(h @ gate_proj^T)
    mma_gemm<EP_NONE>   <<<dim3(DIN/128, ROWS/128), blk128>>>(h, in_proj_w,   nullptr, nullptr, a,  ROWS, DIN, DM);
    mma_gemm<EP_GATEMUL><<<dim3(DIN/128, ROWS/128), blk128>>>(h, gate_proj_w, a,       nullptr, a,  ROWS, DIN, DM);

    // 3. dt = softplus(z @ dt_w^T + dt_b)
    mma_gemm<EP_SOFTPLUS><<<dim3(DIN/128, ROWS/128), blk128>>>(a, dt_w, nullptr, dt_b, bb, ROWS, DIN, DIN);

    // 4. BC = z @ x_proj^T
    bc_kernel<<<ROWS, blk256>>>(x_proj_w);

    // 5. scan
    scan_kernel<<<(BATCH * DIN) / 16, blk256>>>(A_log, Dp);

    // 6. x2 = x + y @ out_proj^T
    mma_gemm<EP_ADD><<<dim3(DM/128, ROWS/128), blk128>>>(y, out_proj_w, x, nullptr, x2, ROWS, DM, DIN);

    // 7. hn = rmsnorm(x2)
    rmsnorm_kernel<<<ROWS, blk256>>>(x2, ffn_norm_w, h);

    // 8. FFN: gg = silu(hn @ Wg^T) * (hn @ Wu^T)
    mma_gemm<EP_NONE>   <<<dim3((FH+127)/128, ROWS/128), blk128>>>(h, ffn_gate_w, nullptr, nullptr, gg, ROWS, FH, DM);
    mma_gemm<EP_SILUMUL><<<dim3((FH+127)/128, ROWS/128), blk128>>>(h, ffn_up_w,   gg,      nullptr, gg, ROWS, FH, DM);

    // 9. out = x2 + gg @ Wd^T
    mma_gemm<EP_ADD><<<dim3(DM/128, ROWS/128), blk128>>>(gg, ffn_down_w, x2, nullptr, out, ROWS, DM, FH);
}